// round 1
// baseline (speedup 1.0000x reference)
#include <cuda_runtime.h>
#include <math.h>

#define B_SZ 2
#define T_SZ 2048
#define C_SZ 1024
#define NH   16
#define HD   64
#define M_SZ (B_SZ*T_SZ)   // 4096

// Scratch (static device globals: allowed; runtime allocation is not)
__device__ float g_q [B_SZ*NH*T_SZ*HD];   // [b][h][t][d]
__device__ float g_kt[B_SZ*NH*HD*T_SZ];   // [b][h][d][t]  (K stored d-major)
__device__ float g_v [B_SZ*NH*T_SZ*HD];   // [b][h][t][d]
__device__ float g_y [M_SZ*C_SZ];         // [b*t][c]

#define MODE_PLAIN   0
#define MODE_HEADS   1
#define MODE_HEADS_T 2

// C = A[M,K] @ W[K,N] + bias, M=4096, K=N=1024. 128x128 tile, 8x8/thread.
template<int MODE>
__global__ __launch_bounds__(256, 2)
void sgemm_kernel(const float* __restrict__ A, const float* __restrict__ W,
                  const float* __restrict__ bias, float* __restrict__ out)
{
    __shared__ float As[8][128];   // transposed: As[k][m]
    __shared__ float Bs[8][128];   // Bs[k][n]

    const int tid = threadIdx.x;
    const int tx  = tid & 15;      // 16 col-groups
    const int ty  = tid >> 4;      // 16 row-groups
    const int bn  = blockIdx.x * 128;
    const int bm  = blockIdx.y * 128;

    const int arow = tid >> 1;             // 0..127
    const int acol = (tid & 1) * 4;        // 0 or 4
    const int brow = tid >> 5;             // 0..7
    const int bcol = (tid & 31) << 2;      // 0..124

    const float* Ap = A + (size_t)(bm + arow) * C_SZ + acol;
    const float* Wp = W + (size_t)brow * C_SZ + bn + bcol;

    float acc[8][8];
    #pragma unroll
    for (int i = 0; i < 8; i++)
        #pragma unroll
        for (int j = 0; j < 8; j++) acc[i][j] = 0.f;

    for (int k0 = 0; k0 < C_SZ; k0 += 8) {
        float4 av = *(const float4*)(Ap + k0);
        As[acol+0][arow] = av.x; As[acol+1][arow] = av.y;
        As[acol+2][arow] = av.z; As[acol+3][arow] = av.w;
        *(float4*)&Bs[brow][bcol] = *(const float4*)(Wp + (size_t)k0 * C_SZ);
        __syncthreads();

        #pragma unroll
        for (int k = 0; k < 8; k++) {
            float a[8], bb[8];
            *(float4*)&a[0]  = *(const float4*)&As[k][ty*4];
            *(float4*)&a[4]  = *(const float4*)&As[k][64 + ty*4];
            *(float4*)&bb[0] = *(const float4*)&Bs[k][tx*4];
            *(float4*)&bb[4] = *(const float4*)&Bs[k][64 + tx*4];
            #pragma unroll
            for (int i = 0; i < 8; i++)
                #pragma unroll
                for (int j = 0; j < 8; j++)
                    acc[i][j] = fmaf(a[i], bb[j], acc[i][j]);
        }
        __syncthreads();
    }

    #pragma unroll
    for (int i = 0; i < 8; i++) {
        const int r = bm + ((i < 4) ? (ty*4 + i) : (64 + ty*4 + i - 4));
        #pragma unroll
        for (int j = 0; j < 8; j++) {
            const int c = bn + ((j < 4) ? (tx*4 + j) : (64 + tx*4 + j - 4));
            const float val = acc[i][j] + bias[c];
            if (MODE == MODE_PLAIN) {
                out[(size_t)r * C_SZ + c] = val;
            } else {
                const int b = r >> 11, t = r & 2047;
                const int h = c >> 6,  d = c & 63;
                if (MODE == MODE_HEADS)
                    out[(((size_t)(b*NH + h)) * T_SZ + t) * HD + d] = val;
                else
                    out[(((size_t)(b*NH + h)) * HD + d) * T_SZ + t] = val;
            }
        }
    }
}

// Flash attention with causal ALiBi. Block: 128 threads, BQ=128 queries,
// BK=64 keys/iter, hd=64. Thread tile 8x8 (ty=rows, tx=strided cols tx+8j).
#define FB_THREADS 128
#define PS_STRIDE  65
#define FLASH_SMEM ((128*64 + 64*64 + 64*64 + 128*PS_STRIDE) * 4)

__global__ __launch_bounds__(FB_THREADS, 2)
void flash_kernel(const float* __restrict__ Q, const float* __restrict__ Kt,
                  const float* __restrict__ V, float* __restrict__ Y)
{
    extern __shared__ float sm[];
    float* Qs = sm;                 // [128][64] row-major
    float* Ks = Qs + 128*64;        // [64 d][64 k] d-major
    float* Vs = Ks + 64*64;         // [64 k][64 d] row-major
    float* Ps = Vs + 64*64;         // [128][PS_STRIDE]

    const int tid = threadIdx.x;
    const int tx  = tid & 7;        // 8 col groups
    const int ty  = tid >> 3;       // 16 row groups
    const int qt  = blockIdx.x;
    const int h   = blockIdx.y;
    const int b   = blockIdx.z;
    const int bh  = b * NH + h;
    const int q0  = qt * 128;

    const float slope = exp2f(-0.5f * (float)(h + 1));
    const float scale = 0.125f;     // 1/sqrt(64)

    // Load Q tile once
    {
        const float* qb = Q + ((size_t)bh * T_SZ + q0) * HD;
        for (int idx = tid; idx < 128*16; idx += FB_THREADS)
            *(float4*)&Qs[idx*4] = *(const float4*)&qb[idx*4];
    }

    float m[8], l[8], acc[8][8];
    #pragma unroll
    for (int i = 0; i < 8; i++) {
        m[i] = -1e30f; l[i] = 0.f;
        #pragma unroll
        for (int j = 0; j < 8; j++) acc[i][j] = 0.f;
    }

    const int nkt = 2*qt + 2;
    for (int kt = 0; kt < nkt; kt++) {
        const int k0 = kt * 64;
        __syncthreads();   // previous iter done with Ks/Vs (also covers Q load)

        {   // K tile: [64 d][64 k], straight strided copy (K is d-major in gmem)
            const float* kb = Kt + (size_t)bh * HD * T_SZ + k0;
            for (int idx = tid; idx < 64*16; idx += FB_THREADS) {
                const int d = idx >> 4, c4 = (idx & 15) << 2;
                *(float4*)&Ks[d*64 + c4] = *(const float4*)&kb[(size_t)d*T_SZ + c4];
            }
            const float* vb = V + ((size_t)bh * T_SZ + k0) * HD;
            for (int idx = tid; idx < 64*16; idx += FB_THREADS)
                *(float4*)&Vs[idx*4] = *(const float4*)&vb[idx*4];
        }
        __syncthreads();

        // S = Q K^T (8x8 per thread)
        float s[8][8];
        #pragma unroll
        for (int i = 0; i < 8; i++)
            #pragma unroll
            for (int j = 0; j < 8; j++) s[i][j] = 0.f;

        #pragma unroll 4
        for (int d = 0; d < 64; d++) {
            float a[8], bb[8];
            #pragma unroll
            for (int i = 0; i < 8; i++) a[i]  = Qs[(ty*8 + i)*64 + d];
            #pragma unroll
            for (int j = 0; j < 8; j++) bb[j] = Ks[d*64 + tx + 8*j];
            #pragma unroll
            for (int i = 0; i < 8; i++)
                #pragma unroll
                for (int j = 0; j < 8; j++)
                    s[i][j] = fmaf(a[i], bb[j], s[i][j]);
        }

        // scale + ALiBi bias + causal mask, online softmax
        const bool need_mask = (k0 + 63 > q0);
        #pragma unroll
        for (int i = 0; i < 8; i++) {
            const int qi = q0 + ty*8 + i;
            float mx = -1e30f;
            #pragma unroll
            for (int j = 0; j < 8; j++) {
                const int ki = k0 + tx + 8*j;
                float sv = s[i][j] * scale - slope * (float)(qi - ki);
                if (need_mask && ki > qi) sv = -1e30f;
                s[i][j] = sv;
                mx = fmaxf(mx, sv);
            }
            #pragma unroll
            for (int o = 1; o < 8; o <<= 1)
                mx = fmaxf(mx, __shfl_xor_sync(0xffffffffu, mx, o));
            const float mnew = fmaxf(m[i], mx);
            const float corr = __expf(m[i] - mnew);
            float ps = 0.f;
            #pragma unroll
            for (int j = 0; j < 8; j++) {
                const float p = __expf(s[i][j] - mnew);
                Ps[(ty*8 + i)*PS_STRIDE + tx + 8*j] = p;
                ps += p;
            }
            #pragma unroll
            for (int o = 1; o < 8; o <<= 1)
                ps += __shfl_xor_sync(0xffffffffu, ps, o);
            l[i] = l[i] * corr + ps;
            m[i] = mnew;
            #pragma unroll
            for (int j = 0; j < 8; j++) acc[i][j] *= corr;
        }
        __syncwarp();   // P rows are shared only among the 8 same-warp tx lanes

        // acc += P @ V
        #pragma unroll 4
        for (int kk = 0; kk < 64; kk++) {
            float a[8], bb[8];
            #pragma unroll
            for (int i = 0; i < 8; i++) a[i]  = Ps[(ty*8 + i)*PS_STRIDE + kk];
            #pragma unroll
            for (int j = 0; j < 8; j++) bb[j] = Vs[kk*64 + tx + 8*j];
            #pragma unroll
            for (int i = 0; i < 8; i++)
                #pragma unroll
                for (int j = 0; j < 8; j++)
                    acc[i][j] = fmaf(a[i], bb[j], acc[i][j]);
        }
    }

    // Write y = acc / l into [b*t][c] layout at column block h*64
    float* yb = Y + ((size_t)(b*T_SZ) + q0) * C_SZ + h*HD;
    #pragma unroll
    for (int i = 0; i < 8; i++) {
        const float inv = 1.0f / l[i];
        const int row = ty*8 + i;
        #pragma unroll
        for (int j = 0; j < 8; j++)
            yb[(size_t)row * C_SZ + tx + 8*j] = acc[i][j] * inv;
    }
}

extern "C" void kernel_launch(void* const* d_in, const int* in_sizes, int n_in,
                              void* d_out, int out_size)
{
    const float* x  = (const float*)d_in[0];
    const float* Wq = (const float*)d_in[1];
    const float* bq = (const float*)d_in[2];
    const float* Wk = (const float*)d_in[3];
    const float* bk = (const float*)d_in[4];
    const float* Wv = (const float*)d_in[5];
    const float* bv = (const float*)d_in[6];
    const float* Wo = (const float*)d_in[7];
    const float* bo = (const float*)d_in[8];
    float* out = (float*)d_out;

    float *qp, *ktp, *vp, *yp;
    cudaGetSymbolAddress((void**)&qp,  g_q);
    cudaGetSymbolAddress((void**)&ktp, g_kt);
    cudaGetSymbolAddress((void**)&vp,  g_v);
    cudaGetSymbolAddress((void**)&yp,  g_y);

    cudaFuncSetAttribute(flash_kernel,
                         cudaFuncAttributeMaxDynamicSharedMemorySize, FLASH_SMEM);

    dim3 gg(C_SZ/128, M_SZ/128);   // (8, 32)
    sgemm_kernel<MODE_HEADS>  <<<gg, 256>>>(x, Wq, bq, qp);
    sgemm_kernel<MODE_HEADS_T><<<gg, 256>>>(x, Wk, bk, ktp);
    sgemm_kernel<MODE_HEADS>  <<<gg, 256>>>(x, Wv, bv, vp);

    flash_kernel<<<dim3(T_SZ/128, NH, B_SZ), FB_THREADS, FLASH_SMEM>>>(qp, ktp, vp, yp);

    sgemm_kernel<MODE_PLAIN>  <<<gg, 256>>>(yp, Wo, bo, out);
}